// round 15
// baseline (speedup 1.0000x reference)
#include <cuda_runtime.h>

// I5Pool: out[b,c,h,w] = max_{j<=w} x[b,c,h,j] * guide[b,0,h,j]
// x [8,256,128,128] fp32, guide [8,1,128,128] fp32.
// Locked best config (ncu 35.36us, bench 43.5us):
//   - 4 channel-rows per warp sharing one guide load (guide L2-resident)
//   - h-inner warp ordering (block covers contiguous 4KB x chunks)
//   - __stcs streaming out stores, warp shuffle max-scan, 4 interleaved rows
//   - 128-thread CTAs (granularity optimum: 256->35.68, 128->35.36, 64->36.22)
// Single change this round: __ldlu (last-use) on x loads — lines deallocate
// from L1/L2 immediately after the read, freeing capacity for guide + stores.

#define B_ 8
#define C_ 256
#define H_ 128
#define W_ 128
#define ROWS   (B_ * C_ * H_)      // 262144
#define RQUAD  (ROWS / 4)          // 65536 warps

__global__ void __launch_bounds__(128) I5Pool_kernel(
    const float* __restrict__ x,
    const float* __restrict__ guide,
    float* __restrict__ out)
{
    const int wg   = (blockIdx.x * blockDim.x + threadIdx.x) >> 5;
    const int lane = threadIdx.x & 31;
    if (wg >= RQUAD) return;

    // wg = b*(C_/4 * H_) + cq*H_ + h ; rows are c = 4*cq + {0,1,2,3}
    const int h  = wg & (H_ - 1);
    const int t  = wg >> 7;               // b*(C_/4) + cq
    const int b  = t >> 6;                // / (C_/4 = 64)
    const int cq = t & 63;

    const size_t rstride = (size_t)H_ * W_;
    const size_t row0 = (((size_t)b * C_ + 4 * cq) * H_ + h) * W_;
    const size_t grow = ((size_t)b * H_ + h) * W_;

    // Front-batch all 5 loads (1 guide cached/L2-resident + 4 x last-use)
    const float4 gv = reinterpret_cast<const float4*>(guide + grow)[lane];
    const float4 x0 = __ldlu(reinterpret_cast<const float4*>(x + row0)               + lane);
    const float4 x1 = __ldlu(reinterpret_cast<const float4*>(x + row0 + rstride)     + lane);
    const float4 x2 = __ldlu(reinterpret_cast<const float4*>(x + row0 + 2 * rstride) + lane);
    const float4 x3 = __ldlu(reinterpret_cast<const float4*>(x + row0 + 3 * rstride) + lane);

    // local serial prefix-max per row
    float a0 = x0.x * gv.x, a1 = fmaxf(a0, x0.y * gv.y);
    float a2 = fmaxf(a1, x0.z * gv.z), a3 = fmaxf(a2, x0.w * gv.w);

    float b0 = x1.x * gv.x, b1 = fmaxf(b0, x1.y * gv.y);
    float b2 = fmaxf(b1, x1.z * gv.z), b3 = fmaxf(b2, x1.w * gv.w);

    float c0 = x2.x * gv.x, c1 = fmaxf(c0, x2.y * gv.y);
    float c2 = fmaxf(c1, x2.z * gv.z), c3 = fmaxf(c2, x2.w * gv.w);

    float d0 = x3.x * gv.x, d1 = fmaxf(d0, x3.y * gv.y);
    float d2 = fmaxf(d1, x3.z * gv.z), d3 = fmaxf(d2, x3.w * gv.w);

    // 4 interleaved warp inclusive max-scans
    float ma = a3, mb = b3, mc = c3, md = d3;
    #pragma unroll
    for (int d = 1; d < 32; d <<= 1) {
        const float oa = __shfl_up_sync(0xffffffffu, ma, d);
        const float ob = __shfl_up_sync(0xffffffffu, mb, d);
        const float oc = __shfl_up_sync(0xffffffffu, mc, d);
        const float od = __shfl_up_sync(0xffffffffu, md, d);
        if (lane >= d) {
            ma = fmaxf(ma, oa); mb = fmaxf(mb, ob);
            mc = fmaxf(mc, oc); md = fmaxf(md, od);
        }
    }
    float pa = __shfl_up_sync(0xffffffffu, ma, 1);
    float pb = __shfl_up_sync(0xffffffffu, mb, 1);
    float pc = __shfl_up_sync(0xffffffffu, mc, 1);
    float pd = __shfl_up_sync(0xffffffffu, md, 1);
    if (lane == 0) {
        const float ninf = __int_as_float(0xff800000);
        pa = ninf; pb = ninf; pc = ninf; pd = ninf;
    }

    float4 o;
    o.x = fmaxf(a0, pa); o.y = fmaxf(a1, pa); o.z = fmaxf(a2, pa); o.w = fmaxf(a3, pa);
    __stcs(reinterpret_cast<float4*>(out + row0)               + lane, o);
    o.x = fmaxf(b0, pb); o.y = fmaxf(b1, pb); o.z = fmaxf(b2, pb); o.w = fmaxf(b3, pb);
    __stcs(reinterpret_cast<float4*>(out + row0 + rstride)     + lane, o);
    o.x = fmaxf(c0, pc); o.y = fmaxf(c1, pc); o.z = fmaxf(c2, pc); o.w = fmaxf(c3, pc);
    __stcs(reinterpret_cast<float4*>(out + row0 + 2 * rstride) + lane, o);
    o.x = fmaxf(d0, pd); o.y = fmaxf(d1, pd); o.z = fmaxf(d2, pd); o.w = fmaxf(d3, pd);
    __stcs(reinterpret_cast<float4*>(out + row0 + 3 * rstride) + lane, o);
}

extern "C" void kernel_launch(void* const* d_in, const int* in_sizes, int n_in,
                              void* d_out, int out_size)
{
    const float* x     = (const float*)d_in[0];
    const float* guide = (const float*)d_in[1];
    float* out         = (float*)d_out;

    const int threads = 128;                    // 4 warps/block
    const int blocks  = (RQUAD * 32) / threads; // 16384 blocks
    I5Pool_kernel<<<blocks, threads>>>(x, guide, out);
}